// round 1
// baseline (speedup 1.0000x reference)
#include <cuda_runtime.h>
#include <math.h>

// Problem constants
#define Nn    10000
#define Ff    64
#define Uu    128
#define Bb    8
#define Ee    160000
#define Mm    5
#define ROWS  (Bb*Nn)      /* 80000 */
#define K1    (Mm*Ff)      /* 320 */
#define K2    (Mm*Uu)      /* 640 */
#define Wd64  512          /* F*B  */
#define Wd128 1024         /* U*B  */

// ---------------- scratch (device globals; no runtime alloc) ----------------
__device__ float g_x0 [(size_t)Nn*Wd64];     // x in (N,F,B) node-major
__device__ float g_tmp[(size_t)Nn*Wd128];    // chaining buffer (max width)
__device__ float g_c0 [(size_t)Nn*Wd128];    // tanh(gconv2) in (N,U,B)
__device__ float g_A64[(size_t)ROWS*K1];     // packed X for gconv1/2: [b*N+n][f*5+m]
__device__ float g_A2 [(size_t)ROWS*K2];     // packed X for gconv3:   [b*N+n][u*5+m]
__device__ float g_theta[(size_t)ROWS*Ff];   // sigmoid(gconv1)
__device__ int   g_deg   [2*Nn];
__device__ int   g_rowptr[2*(Nn+1)];
__device__ int   g_pos   [2*Nn];
__device__ int   g_csr_src[2*Ee];
__device__ float g_csr_w  [2*Ee];
__device__ int   g_csr_eid[2*Ee];

// ---------------- CSR construction (deterministic) ----------------
__global__ void k_zero_deg() {
    int i = blockIdx.x * blockDim.x + threadIdx.x;
    if (i < 2 * Nn) g_deg[i] = 0;
}

__global__ void k_hist(const int* __restrict__ er, const int* __restrict__ ec) {
    int e = blockIdx.x * blockDim.x + threadIdx.x;
    if (e >= Ee) return;
    atomicAdd(&g_deg[ec[e]], 1);        // support1: dst = cols
    atomicAdd(&g_deg[Nn + er[e]], 1);   // support2: dst = rows
}

// one block per support, 1024 threads; exclusive prefix-sum of degrees
__global__ void k_scan() {
    int sup = blockIdx.x;
    __shared__ int sh[1024];
    __shared__ int carry_s;
    if (threadIdx.x == 0) carry_s = 0;
    __syncthreads();
    for (int base = 0; base < Nn; base += 1024) {
        int i = base + threadIdx.x;
        int v = (i < Nn) ? g_deg[sup * Nn + i] : 0;
        sh[threadIdx.x] = v;
        __syncthreads();
        for (int off = 1; off < 1024; off <<= 1) {
            int t = 0;
            if (threadIdx.x >= off) t = sh[threadIdx.x - off];
            __syncthreads();
            sh[threadIdx.x] += t;
            __syncthreads();
        }
        int excl = sh[threadIdx.x] - v;
        int c = carry_s;
        if (i < Nn) {
            g_rowptr[sup * (Nn + 1) + i] = c + excl;
            g_pos[sup * Nn + i] = c + excl;
        }
        __syncthreads();
        if (threadIdx.x == 1023) carry_s += sh[1023];
        __syncthreads();
    }
    if (threadIdx.x == 0) g_rowptr[sup * (Nn + 1) + Nn] = carry_s;
}

__global__ void k_fill(const int* __restrict__ er, const int* __restrict__ ec,
                       const float* __restrict__ w1, const float* __restrict__ w2) {
    int e = blockIdx.x * blockDim.x + threadIdx.x;
    if (e >= Ee) return;
    {   // support1: dst = cols[e], src = rows[e]
        int p = atomicAdd(&g_pos[ec[e]], 1);
        g_csr_src[p] = er[e]; g_csr_w[p] = w1[e]; g_csr_eid[p] = e;
    }
    {   // support2: dst = rows[e], src = cols[e]
        int p = atomicAdd(&g_pos[Nn + er[e]], 1) + Ee;
        g_csr_src[p] = ec[e]; g_csr_w[p] = w2[e]; g_csr_eid[p] = e;
    }
}

// per-row insertion sort by original edge id -> deterministic accumulation order
__global__ void k_sortrows() {
    int idx = blockIdx.x * blockDim.x + threadIdx.x;
    if (idx >= 2 * Nn) return;
    int sup = idx / Nn, n = idx % Nn;
    int base = sup * Ee;
    int beg = g_rowptr[sup * (Nn + 1) + n] + base;
    int end = g_rowptr[sup * (Nn + 1) + n + 1] + base;
    for (int i = beg + 1; i < end; i++) {
        int   ke = g_csr_eid[i];
        int   ks = g_csr_src[i];
        float kw = g_csr_w[i];
        int j = i - 1;
        while (j >= beg && g_csr_eid[j] > ke) {
            g_csr_eid[j + 1] = g_csr_eid[j];
            g_csr_src[j + 1] = g_csr_src[j];
            g_csr_w  [j + 1] = g_csr_w[j];
            j--;
        }
        g_csr_eid[j + 1] = ke;
        g_csr_src[j + 1] = ks;
        g_csr_w  [j + 1] = kw;
    }
}

// ---------------- transpose: y(B,N,F) -> x0(N,F,B) + pack A64 m=0 ----------------
__global__ void k_transpose(const float* __restrict__ y) {
    long idx = (long)blockIdx.x * blockDim.x + threadIdx.x;
    if (idx >= (long)Bb * Nn * Ff) return;
    int f = (int)(idx & 63);
    long t = idx >> 6;
    int n = (int)(t % Nn);
    int b = (int)(t / Nn);
    float v = y[idx];  // y flat = b*N*64 + n*64 + f
    g_x0[(size_t)n * Wd64 + f * Bb + b] = v;
    g_A64[((size_t)b * Nn + n) * K1 + f * Mm + 0] = v;
}

// ---------------- SPMM: out[n] = (2*)S x (- prev) ; dual-write node-major + packed A ----------------
template<int ELEMS>
__global__ __launch_bounds__(512)
void k_spmm(const int* __restrict__ rowptr, const int* __restrict__ src,
            const float* __restrict__ w, const float* __restrict__ xin,
            const float* __restrict__ prev, float* __restrict__ out_node,
            float* __restrict__ outA, int m, int KA)
{
    const int Wd = 512 * ELEMS;
    int n = blockIdx.x;
    int tid = threadIdx.x;
    float acc[ELEMS];
#pragma unroll
    for (int j = 0; j < ELEMS; j++) acc[j] = 0.f;

    int beg = rowptr[n], end = rowptr[n + 1];
    int e = beg;
    for (; e + 4 <= end; e += 4) {                 // MLP=4 to hide L2 latency
        int   s0 = src[e],   s1 = src[e+1],   s2 = src[e+2],   s3 = src[e+3];
        float w0 = w[e],     w1 = w[e+1],     w2 = w[e+2],     w3 = w[e+3];
#pragma unroll
        for (int j = 0; j < ELEMS; j++) {
            int o = tid + 512 * j;
            float v0 = xin[(size_t)s0 * Wd + o];
            float v1 = xin[(size_t)s1 * Wd + o];
            float v2 = xin[(size_t)s2 * Wd + o];
            float v3 = xin[(size_t)s3 * Wd + o];
            acc[j] += w0 * v0;
            acc[j] += w1 * v1;
            acc[j] += w2 * v2;
            acc[j] += w3 * v3;
        }
    }
    for (; e < end; e++) {
        int s = src[e]; float wt = w[e];
#pragma unroll
        for (int j = 0; j < ELEMS; j++)
            acc[j] += wt * xin[(size_t)s * Wd + tid + 512 * j];
    }

#pragma unroll
    for (int j = 0; j < ELEMS; j++) {
        int idx = tid + 512 * j;
        float v = acc[j];
        if (prev)     v = 2.f * v - prev[(size_t)n * Wd + idx];
        if (out_node) out_node[(size_t)n * Wd + idx] = v;
        int f = idx >> 3, b = idx & 7;
        outA[((size_t)b * Nn + n) * KA + f * Mm + m] = v;
    }
}

// ---------------- fused SGEMM: C(80000 x BN) = A(80000 x K) @ W(K x BN) + epilogue ----------------
// MODE 0: theta = sigmoid(. + b_lat)              -> out[row*64+co]
// MODE 1: v = tanh(. + b_units); c0(N,U,B) + A2 m=0
// MODE 2: out = -theta * tanh(. + b_lat)          -> d_out[row*64+co]
template<int BN, int TN, int MODE>
__global__ __launch_bounds__(256)
void k_gemm(const float* __restrict__ A, int K,
            const float* __restrict__ Wt, const float* __restrict__ bias,
            float* __restrict__ out, float* __restrict__ aux)
{
    __shared__ float As[16][132];
    __shared__ float Bs[16][BN + 4];
    int tid = threadIdx.x;
    int tx = tid & 15, ty = tid >> 4;

    float acc[8][TN];
#pragma unroll
    for (int i = 0; i < 8; i++)
#pragma unroll
        for (int j = 0; j < TN; j++) acc[i][j] = 0.f;

    const float* Ab = A + (size_t)blockIdx.x * 128 * K;
    int nkb = K / 16;
    for (int kb = 0; kb < nkb; kb++) {
        // A tile 128x16, transposed into As[k][row]
#pragma unroll
        for (int q = 0; q < 2; q++) {
            int i = tid + q * 256;
            int r = i >> 2, kq = i & 3;
            float4 v = *(const float4*)(Ab + (size_t)r * K + kb * 16 + kq * 4);
            As[kq * 4 + 0][r] = v.x;
            As[kq * 4 + 1][r] = v.y;
            As[kq * 4 + 2][r] = v.z;
            As[kq * 4 + 3][r] = v.w;
        }
        // W tile 16xBN
#pragma unroll
        for (int q = 0; q < BN / 64; q++) {
            int i = tid + q * 256;
            int kk = i / (BN / 4), c4 = i % (BN / 4);
            float4 v = *(const float4*)(Wt + (size_t)(kb * 16 + kk) * BN + c4 * 4);
            *(float4*)&Bs[kk][c4 * 4] = v;
        }
        __syncthreads();
#pragma unroll
        for (int kk = 0; kk < 16; kk++) {
            float a[8];
            *(float4*)&a[0] = *(const float4*)&As[kk][ty * 8];
            *(float4*)&a[4] = *(const float4*)&As[kk][ty * 8 + 4];
            float b[TN];
#pragma unroll
            for (int q = 0; q < TN / 4; q++)
                *(float4*)&b[q * 4] = *(const float4*)&Bs[kk][tx * TN + q * 4];
#pragma unroll
            for (int i = 0; i < 8; i++)
#pragma unroll
                for (int j = 0; j < TN; j++)
                    acc[i][j] += a[i] * b[j];
        }
        __syncthreads();
    }

#pragma unroll
    for (int i = 0; i < 8; i++) {
        int row = blockIdx.x * 128 + ty * 8 + i;   // row = b*N + n
#pragma unroll
        for (int j = 0; j < TN; j++) {
            int co = tx * TN + j;
            float v = acc[i][j];
            if (MODE == 0) {
                v += __ldg(&bias[co]);
                out[(size_t)row * 64 + co] = 1.f / (1.f + __expf(-v));
            } else if (MODE == 1) {
                v = tanhf(v + __ldg(&bias[co]));
                int b = row / Nn, n = row % Nn;
                out[(size_t)n * Wd128 + co * Bb + b] = v;       // c0 node-major
                aux[(size_t)row * K2 + co * Mm + 0] = v;        // A2 m=0
            } else {
                v = tanhf(v + __ldg(&bias[co]));
                out[(size_t)row * 64 + co] = -__ldg(&aux[(size_t)row * 64 + co]) * v;
            }
        }
    }
}

// ---------------- host launch ----------------
extern "C" void kernel_launch(void* const* d_in, const int* in_sizes, int n_in,
                              void* d_out, int out_size)
{
    (void)in_sizes; (void)n_in; (void)out_size;
    const float* y       = (const float*)d_in[0];
    const float* W_lat   = (const float*)d_in[1];
    const float* b_lat   = (const float*)d_in[2];
    const float* W_units = (const float*)d_in[3];
    const float* b_units = (const float*)d_in[4];
    const float* W_fin   = (const float*)d_in[5];
    const float* s1w     = (const float*)d_in[6];
    const float* s2w     = (const float*)d_in[7];
    const int*   erows   = (const int*)d_in[8];
    const int*   ecols   = (const int*)d_in[9];
    float* out = (float*)d_out;

    void *px0, *ptmp, *pc0, *pA64, *pA2, *pth, *prp, *psrc, *pw;
    cudaGetSymbolAddress(&px0,  g_x0);
    cudaGetSymbolAddress(&ptmp, g_tmp);
    cudaGetSymbolAddress(&pc0,  g_c0);
    cudaGetSymbolAddress(&pA64, g_A64);
    cudaGetSymbolAddress(&pA2,  g_A2);
    cudaGetSymbolAddress(&pth,  g_theta);
    cudaGetSymbolAddress(&prp,  g_rowptr);
    cudaGetSymbolAddress(&psrc, g_csr_src);
    cudaGetSymbolAddress(&pw,   g_csr_w);

    float* x0   = (float*)px0;
    float* tmp  = (float*)ptmp;
    float* c0   = (float*)pc0;
    float* A64  = (float*)pA64;
    float* A2   = (float*)pA2;
    float* th   = (float*)pth;
    int*   rp   = (int*)prp;
    int*   csrc = (int*)psrc;
    float* cw   = (float*)pw;

    // --- CSR build (deterministic) ---
    k_zero_deg<<<(2 * Nn + 255) / 256, 256>>>();
    k_hist<<<(Ee + 255) / 256, 256>>>(erows, ecols);
    k_scan<<<2, 1024>>>();
    k_fill<<<(Ee + 255) / 256, 256>>>(erows, ecols, s1w, s2w);
    k_sortrows<<<(2 * Nn + 255) / 256, 256>>>();

    // --- x0 + A64[m=0] ---
    k_transpose<<<((long)Bb * Nn * Ff + 255) / 256, 256>>>(y);

    const int* rp1 = rp;            const int* rp2 = rp + (Nn + 1);
    const int* sr1 = csrc;          const int* sr2 = csrc + Ee;
    const float* w1 = cw;           const float* w2 = cw + Ee;

    // --- shared diffusion states (F=64 width), pack A64 m=1..4 ---
    k_spmm<1><<<Nn, 512>>>(rp1, sr1, w1, x0,  nullptr, tmp,     A64, 1, K1);
    k_spmm<1><<<Nn, 512>>>(rp1, sr1, w1, tmp, x0,      nullptr, A64, 2, K1);
    k_spmm<1><<<Nn, 512>>>(rp2, sr2, w2, x0,  nullptr, tmp,     A64, 3, K1);
    k_spmm<1><<<Nn, 512>>>(rp2, sr2, w2, tmp, x0,      nullptr, A64, 4, K1);

    // --- gconv1: theta = sigmoid(A64 @ W_lat + b_lat) ---
    k_gemm<64, 4, 0><<<ROWS / 128, 256>>>(A64, K1, W_lat, b_lat, th, nullptr);
    // --- gconv2: c0 = tanh(A64 @ W_units + b_units); also A2 m=0 ---
    k_gemm<128, 8, 1><<<ROWS / 128, 256>>>(A64, K1, W_units, b_units, c0, A2);

    // --- gconv3 diffusion (U=128 width), pack A2 m=1..4 ---
    k_spmm<2><<<Nn, 512>>>(rp1, sr1, w1, c0,  nullptr, tmp,     A2, 1, K2);
    k_spmm<2><<<Nn, 512>>>(rp1, sr1, w1, tmp, c0,      nullptr, A2, 2, K2);
    k_spmm<2><<<Nn, 512>>>(rp2, sr2, w2, c0,  nullptr, tmp,     A2, 3, K2);
    k_spmm<2><<<Nn, 512>>>(rp2, sr2, w2, tmp, c0,      nullptr, A2, 4, K2);

    // --- gconv3 + fuse: out = -theta * tanh(A2 @ W_final + b_lat) ---
    k_gemm<64, 4, 2><<<ROWS / 128, 256>>>(A2, K2, W_fin, b_lat, out, th);
}

// round 3
// speedup vs baseline: 1.7461x; 1.7461x over previous
#include <cuda_runtime.h>
#include <cuda_bf16.h>
#include <math.h>
#include <stdint.h>

// Problem constants
#define Nn    10000
#define Ff    64
#define Uu    128
#define Bb    8
#define Ee    160000
#define Mm    5
#define ROWS  (Bb*Nn)      /* 80000 */
#define K1    (Mm*Ff)      /* 320 */
#define K2    (Mm*Uu)      /* 640 */
#define Wd64  512          /* F*B  */
#define Wd128 1024         /* U*B  */

// ================= scratch (device globals; no runtime alloc) =================
// node-major fp32 buffers use width index o = b*Fw + f
__device__ __align__(128) float g_x0 [(size_t)Nn*Wd64];
__device__ __align__(128) float g_tmp[(size_t)Nn*Wd128];
__device__ __align__(128) float g_c0 [(size_t)Nn*Wd128];
__device__ __align__(128) __nv_bfloat16 g_A64h[(size_t)ROWS*K1];  // [row][m*64+f]
__device__ __align__(128) __nv_bfloat16 g_A64l[(size_t)ROWS*K1];
__device__ __align__(128) __nv_bfloat16 g_A2h [(size_t)ROWS*K2];  // [row][m*128+u]
__device__ __align__(128) __nv_bfloat16 g_A2l [(size_t)ROWS*K2];
__device__ __align__(128) float g_theta[(size_t)ROWS*Ff];
__device__ __align__(128) __nv_bfloat16 g_Bch[192*K1], g_Bcl[192*K1]; // [W_lat|W_units]^T
__device__ __align__(128) __nv_bfloat16 g_B3h[64*K2],  g_B3l[64*K2];  // W_final^T
__device__ int   g_deg   [2*Nn];
__device__ int   g_rowptr[2*(Nn+1)];
__device__ int   g_pos   [2*Nn];
__device__ int   g_csr_src[2*Ee];
__device__ float g_csr_w  [2*Ee];
__device__ int   g_csr_eid[2*Ee];

// ================= helpers =================
__device__ __forceinline__ uint32_t smem_u32(const void* p) {
    uint32_t a;
    asm("{ .reg .u64 t; cvta.to.shared.u64 t, %1; cvt.u32.u64 %0, t; }" : "=r"(a) : "l"(p));
    return a;
}
__device__ __forceinline__ void cp16(uint32_t s, const void* g) {
    asm volatile("cp.async.cg.shared.global [%0], [%1], 16;" :: "r"(s), "l"(g));
}
__device__ __forceinline__ void cp_commit() {
    asm volatile("cp.async.commit_group;");
}
template<int N> __device__ __forceinline__ void cp_wait() {
    asm volatile("cp.async.wait_group %0;" :: "n"(N));
}
__device__ __forceinline__ void mma16816(float* c, const uint32_t* a, const uint32_t* b) {
    asm volatile("mma.sync.aligned.m16n8k16.row.col.f32.bf16.bf16.f32 "
        "{%0,%1,%2,%3}, {%4,%5,%6,%7}, {%8,%9}, {%0,%1,%2,%3};"
        : "+f"(c[0]), "+f"(c[1]), "+f"(c[2]), "+f"(c[3])
        : "r"(a[0]), "r"(a[1]), "r"(a[2]), "r"(a[3]), "r"(b[0]), "r"(b[1]));
}

// ================= CSR construction (deterministic) =================
__global__ void k_zero_deg() {
    int i = blockIdx.x * blockDim.x + threadIdx.x;
    if (i < 2 * Nn) g_deg[i] = 0;
}
__global__ void k_hist(const int* __restrict__ er, const int* __restrict__ ec) {
    int e = blockIdx.x * blockDim.x + threadIdx.x;
    if (e >= Ee) return;
    atomicAdd(&g_deg[ec[e]], 1);
    atomicAdd(&g_deg[Nn + er[e]], 1);
}
__global__ void k_scan() {
    int sup = blockIdx.x;
    __shared__ int sh[1024];
    __shared__ int carry_s;
    if (threadIdx.x == 0) carry_s = 0;
    __syncthreads();
    for (int base = 0; base < Nn; base += 1024) {
        int i = base + threadIdx.x;
        int v = (i < Nn) ? g_deg[sup * Nn + i] : 0;
        sh[threadIdx.x] = v;
        __syncthreads();
        for (int off = 1; off < 1024; off <<= 1) {
            int t = 0;
            if (threadIdx.x >= off) t = sh[threadIdx.x - off];
            __syncthreads();
            sh[threadIdx.x] += t;
            __syncthreads();
        }
        int excl = sh[threadIdx.x] - v;
        int c = carry_s;
        if (i < Nn) {
            g_rowptr[sup * (Nn + 1) + i] = c + excl;
            g_pos[sup * Nn + i] = c + excl;
        }
        __syncthreads();
        if (threadIdx.x == 1023) carry_s += sh[1023];
        __syncthreads();
    }
    if (threadIdx.x == 0) g_rowptr[sup * (Nn + 1) + Nn] = carry_s;
}
__global__ void k_fill(const int* __restrict__ er, const int* __restrict__ ec,
                       const float* __restrict__ w1, const float* __restrict__ w2) {
    int e = blockIdx.x * blockDim.x + threadIdx.x;
    if (e >= Ee) return;
    {
        int p = atomicAdd(&g_pos[ec[e]], 1);
        g_csr_src[p] = er[e]; g_csr_w[p] = w1[e]; g_csr_eid[p] = e;
    }
    {
        int p = atomicAdd(&g_pos[Nn + er[e]], 1) + Ee;
        g_csr_src[p] = ec[e]; g_csr_w[p] = w2[e]; g_csr_eid[p] = e;
    }
}
__global__ void k_sortrows() {
    int idx = blockIdx.x * blockDim.x + threadIdx.x;
    if (idx >= 2 * Nn) return;
    int sup = idx / Nn, n = idx % Nn;
    int base = sup * Ee;
    int beg = g_rowptr[sup * (Nn + 1) + n] + base;
    int end = g_rowptr[sup * (Nn + 1) + n + 1] + base;
    for (int i = beg + 1; i < end; i++) {
        int ke = g_csr_eid[i], ks = g_csr_src[i];
        float kw = g_csr_w[i];
        int j = i - 1;
        while (j >= beg && g_csr_eid[j] > ke) {
            g_csr_eid[j + 1] = g_csr_eid[j];
            g_csr_src[j + 1] = g_csr_src[j];
            g_csr_w  [j + 1] = g_csr_w[j];
            j--;
        }
        g_csr_eid[j + 1] = ke; g_csr_src[j + 1] = ks; g_csr_w[j + 1] = kw;
    }
}

// ================= weight prep: transpose + m-major permute + bf16 hi/lo =================
__global__ void k_wprep(const float* __restrict__ Wl, const float* __restrict__ Wu,
                        const float* __restrict__ Wf) {
    int i = blockIdx.x * blockDim.x + threadIdx.x;
    float v; __nv_bfloat16 *ph, *pl; int di;
    if (i < 192 * K1) {                    // combined [W_lat | W_units]^T, k = m*64+f
        int n = i / K1, k = i % K1;
        int m = k / 64, f = k % 64;
        v = (n < 64) ? Wl[(f * Mm + m) * 64 + n]
                     : Wu[(f * Mm + m) * 128 + (n - 64)];
        ph = g_Bch; pl = g_Bcl; di = i;
    } else if (i < 192 * K1 + 64 * K2) {   // W_final^T, k = m*128+u
        int j = i - 192 * K1;
        int n = j / K2, k = j % K2;
        int m = k / 128, u = k % 128;
        v = Wf[(u * Mm + m) * 64 + n];
        ph = g_B3h; pl = g_B3l; di = j;
    } else return;
    __nv_bfloat16 h = __float2bfloat16(v);
    ph[di] = h;
    pl[di] = __float2bfloat16(v - __bfloat162float(h));
}

// ================= transpose: y(B,N,F) -> x0(N, b*64+f) + A64 m=0 =================
__global__ void k_transpose(const float* __restrict__ y) {
    long idx = (long)blockIdx.x * blockDim.x + threadIdx.x;
    if (idx >= (long)Bb * Nn * Ff) return;
    int f = (int)(idx & 63);
    long t = idx >> 6;
    int n = (int)(t % Nn);
    int b = (int)(t / Nn);
    float v = y[idx];
    g_x0[(size_t)n * Wd64 + b * 64 + f] = v;
    size_t row = (size_t)b * Nn + n;
    __nv_bfloat16 h = __float2bfloat16(v);
    g_A64h[row * K1 + f] = h;
    g_A64l[row * K1 + f] = __float2bfloat16(v - __bfloat162float(h));
}

// ================= SPMM: fp32 gather; width index o = b*Fw + f =================
template<int ELEMS>
__global__ __launch_bounds__(512)
void k_spmm(const int* __restrict__ rowptr, const int* __restrict__ src,
            const float* __restrict__ w, const float* __restrict__ xin,
            const float* __restrict__ prev, float* __restrict__ out_node,
            __nv_bfloat16* __restrict__ Ah, __nv_bfloat16* __restrict__ Al,
            int m, int KA)
{
    const int Wd = 512 * ELEMS;
    const int Fw = 64 * ELEMS;
    int n = blockIdx.x;
    int tid = threadIdx.x;
    float acc[ELEMS];
#pragma unroll
    for (int j = 0; j < ELEMS; j++) acc[j] = 0.f;

    int beg = rowptr[n], end = rowptr[n + 1];
    int e = beg;
    for (; e + 4 <= end; e += 4) {
        int   s0 = src[e], s1 = src[e+1], s2 = src[e+2], s3 = src[e+3];
        float w0 = w[e],   w1 = w[e+1],   w2 = w[e+2],   w3 = w[e+3];
#pragma unroll
        for (int j = 0; j < ELEMS; j++) {
            int o = tid + 512 * j;
            acc[j] += w0 * xin[(size_t)s0 * Wd + o];
            acc[j] += w1 * xin[(size_t)s1 * Wd + o];
            acc[j] += w2 * xin[(size_t)s2 * Wd + o];
            acc[j] += w3 * xin[(size_t)s3 * Wd + o];
        }
    }
    for (; e < end; e++) {
        int s = src[e]; float wt = w[e];
#pragma unroll
        for (int j = 0; j < ELEMS; j++)
            acc[j] += wt * xin[(size_t)s * Wd + tid + 512 * j];
    }

#pragma unroll
    for (int j = 0; j < ELEMS; j++) {
        int o = tid + 512 * j;
        float v = acc[j];
        if (prev)     v = 2.f * v - prev[(size_t)n * Wd + o];
        if (out_node) out_node[(size_t)n * Wd + o] = v;
        int b = o / Fw, f = o % Fw;
        size_t dst = ((size_t)b * Nn + n) * KA + m * Fw + f;
        __nv_bfloat16 h = __float2bfloat16(v);
        Ah[dst] = h;
        Al[dst] = __float2bfloat16(v - __bfloat162float(h));
    }
}

// ================= bf16-split HMMA GEMM =================
// C(128 x BN) = (Ah+Al)(128 x K) @ (Bh+Bl)(K x BN); B stored [BN][K] K-major.
// MODE 0 (BN=192): col<64 -> theta = sigmoid(.+b_lat); col>=64 -> t=tanh(.+b_units),
//                  c0[(n,b*128+u)] = t, A2 m=0 (bf16 hi/lo)
// MODE 1 (BN=64):  out = -theta * tanh(. + b_lat)
template<int BN, int MODE>
__global__ __launch_bounds__(256, 1)
void k_mma(const __nv_bfloat16* __restrict__ Ahi, const __nv_bfloat16* __restrict__ Alo,
           int K,
           const __nv_bfloat16* __restrict__ Bhi, const __nv_bfloat16* __restrict__ Blo,
           const float* __restrict__ bias_a, const float* __restrict__ bias_b,
           float* __restrict__ theta, float* __restrict__ c0,
           __nv_bfloat16* __restrict__ A2h, __nv_bfloat16* __restrict__ A2l,
           float* __restrict__ outp)
{
    constexpr int WN = BN / 2;       // warp n-extent
    constexpr int NT = WN / 8;       // n8 tiles per warp
    constexpr int RSTRIDE = 80;      // 40 bf16 row stride (bank-shift 20)
    constexpr int ABYTES = 128 * RSTRIDE;
    constexpr int BBYTES = BN * RSTRIDE;
    constexpr int STAGE = 2 * ABYTES + 2 * BBYTES;

    extern __shared__ __align__(128) char sm[];
    const int tid = threadIdx.x;
    const int lane = tid & 31, wid = tid >> 5;
    const int wm = wid & 3, wn = wid >> 2;
    const size_t rb = (size_t)blockIdx.x * 128;
    const int S = K / 32;

    float acc[2][NT][4];
#pragma unroll
    for (int a = 0; a < 2; a++)
#pragma unroll
        for (int b = 0; b < NT; b++)
#pragma unroll
            for (int c = 0; c < 4; c++) acc[a][b][c] = 0.f;

    auto load_stage = [&](int kc, int s) {
        uint32_t sa = smem_u32(sm + (size_t)s * STAGE);
#pragma unroll
        for (int it = 0; it < 2; it++) {
            int i = tid + it * 256;
            int r = i >> 2, q = i & 3;
            size_t g = (rb + r) * (size_t)K + kc * 32 + q * 8;
            cp16(sa + r * RSTRIDE + q * 16, Ahi + g);
            cp16(sa + ABYTES + r * RSTRIDE + q * 16, Alo + g);
        }
#pragma unroll
        for (int it = 0; it < BN / 64; it++) {
            int i = tid + it * 256;
            int r = i >> 2, q = i & 3;
            size_t g = (size_t)r * K + kc * 32 + q * 8;
            cp16(sa + 2 * ABYTES + r * RSTRIDE + q * 16, Bhi + g);
            cp16(sa + 2 * ABYTES + BBYTES + r * RSTRIDE + q * 16, Blo + g);
        }
        cp_commit();
    };

    load_stage(0, 0);

    for (int kc = 0; kc < S; kc++) {
        if (kc + 1 < S) {
            load_stage(kc + 1, (kc + 1) & 1);
            cp_wait<1>();
        } else {
            cp_wait<0>();
        }
        __syncthreads();

        const char* st = sm + (size_t)(kc & 1) * STAGE;
        const char* Ah_s = st;
        const char* Al_s = st + ABYTES;
        const char* Bh_s = st + 2 * ABYTES;
        const char* Bl_s = st + 2 * ABYTES + BBYTES;
        const int kq = 2 * (lane & 3);   // element-k offset for this lane

#pragma unroll
        for (int k16 = 0; k16 < 2; k16++) {
            const int kb = (k16 * 16 + kq) * 2;   // byte offset along k
            uint32_t ah[2][4], al[2][4];
#pragma unroll
            for (int mt = 0; mt < 2; mt++) {
                int r = wm * 32 + mt * 16 + (lane >> 2);
                ah[mt][0] = *(const uint32_t*)(Ah_s + r * RSTRIDE + kb);
                ah[mt][1] = *(const uint32_t*)(Ah_s + (r + 8) * RSTRIDE + kb);
                ah[mt][2] = *(const uint32_t*)(Ah_s + r * RSTRIDE + kb + 16);
                ah[mt][3] = *(const uint32_t*)(Ah_s + (r + 8) * RSTRIDE + kb + 16);
                al[mt][0] = *(const uint32_t*)(Al_s + r * RSTRIDE + kb);
                al[mt][1] = *(const uint32_t*)(Al_s + (r + 8) * RSTRIDE + kb);
                al[mt][2] = *(const uint32_t*)(Al_s + r * RSTRIDE + kb + 16);
                al[mt][3] = *(const uint32_t*)(Al_s + (r + 8) * RSTRIDE + kb + 16);
            }
#pragma unroll
            for (int nt = 0; nt < NT; nt++) {
                int nr = wn * WN + nt * 8 + (lane >> 2);
                uint32_t bh[2], bl[2];
                bh[0] = *(const uint32_t*)(Bh_s + nr * RSTRIDE + kb);
                bh[1] = *(const uint32_t*)(Bh_s + nr * RSTRIDE + kb + 16);
                bl[0] = *(const uint32_t*)(Bl_s + nr * RSTRIDE + kb);
                bl[1] = *(const uint32_t*)(Bl_s + nr * RSTRIDE + kb + 16);
#pragma unroll
                for (int mt = 0; mt < 2; mt++) {
                    mma16816(acc[mt][nt], ah[mt], bh);
                    mma16816(acc[mt][nt], al[mt], bh);
                    mma16816(acc[mt][nt], ah[mt], bl);
                }
            }
        }
        __syncthreads();
    }

    // ---- epilogue ----
    const int r0 = lane >> 2, cq = (lane & 3) * 2;
#pragma unroll
    for (int mt = 0; mt < 2; mt++) {
#pragma unroll
        for (int nt = 0; nt < NT; nt++) {
#pragma unroll
            for (int e = 0; e < 4; e++) {
                int row = (int)rb + wm * 32 + mt * 16 + r0 + ((e >> 1) << 3);
                int col = wn * WN + nt * 8 + cq + (e & 1);
                float v = acc[mt][nt][e];
                if (MODE == 0) {
                    if (col < 64) {
                        float t = 1.f / (1.f + __expf(-(v + __ldg(&bias_a[col]))));
                        theta[(size_t)row * 64 + col] = t;
                    } else {
                        int u = col - 64;
                        float t = tanhf(v + __ldg(&bias_b[u]));
                        int b = row / Nn, n = row % Nn;
                        c0[(size_t)n * Wd128 + b * 128 + u] = t;
                        __nv_bfloat16 h = __float2bfloat16(t);
                        size_t dst = (size_t)row * K2 + u;
                        A2h[dst] = h;
                        A2l[dst] = __float2bfloat16(t - __bfloat162float(h));
                    }
                } else {
                    float t = tanhf(v + __ldg(&bias_a[col]));
                    outp[(size_t)row * 64 + col] =
                        -__ldg(&theta[(size_t)row * 64 + col]) * t;
                }
            }
        }
    }
}

// ================= host launch =================
extern "C" void kernel_launch(void* const* d_in, const int* in_sizes, int n_in,
                              void* d_out, int out_size)
{
    (void)in_sizes; (void)n_in; (void)out_size;
    const float* y       = (const float*)d_in[0];
    const float* W_lat   = (const float*)d_in[1];
    const float* b_lat   = (const float*)d_in[2];
    const float* W_units = (const float*)d_in[3];
    const float* b_units = (const float*)d_in[4];
    const float* W_fin   = (const float*)d_in[5];
    const float* s1w     = (const float*)d_in[6];
    const float* s2w     = (const float*)d_in[7];
    const int*   erows   = (const int*)d_in[8];
    const int*   ecols   = (const int*)d_in[9];
    float* out = (float*)d_out;

    void *px0, *ptmp, *pc0, *pth, *prp, *psrc, *pw;
    void *pA64h, *pA64l, *pA2h, *pA2l, *pBch, *pBcl, *pB3h, *pB3l;
    cudaGetSymbolAddress(&px0,  g_x0);
    cudaGetSymbolAddress(&ptmp, g_tmp);
    cudaGetSymbolAddress(&pc0,  g_c0);
    cudaGetSymbolAddress(&pth,  g_theta);
    cudaGetSymbolAddress(&prp,  g_rowptr);
    cudaGetSymbolAddress(&psrc, g_csr_src);
    cudaGetSymbolAddress(&pw,   g_csr_w);
    cudaGetSymbolAddress(&pA64h, g_A64h); cudaGetSymbolAddress(&pA64l, g_A64l);
    cudaGetSymbolAddress(&pA2h,  g_A2h);  cudaGetSymbolAddress(&pA2l,  g_A2l);
    cudaGetSymbolAddress(&pBch,  g_Bch);  cudaGetSymbolAddress(&pBcl,  g_Bcl);
    cudaGetSymbolAddress(&pB3h,  g_B3h);  cudaGetSymbolAddress(&pB3l,  g_B3l);

    float* x0  = (float*)px0;
    float* tmp = (float*)ptmp;
    float* c0  = (float*)pc0;
    float* th  = (float*)pth;
    int*   rp  = (int*)prp;
    int*   csrc = (int*)psrc;
    float* cw  = (float*)pw;
    __nv_bfloat16 *A64h = (__nv_bfloat16*)pA64h, *A64l = (__nv_bfloat16*)pA64l;
    __nv_bfloat16 *A2h  = (__nv_bfloat16*)pA2h,  *A2l  = (__nv_bfloat16*)pA2l;
    __nv_bfloat16 *Bch  = (__nv_bfloat16*)pBch,  *Bcl  = (__nv_bfloat16*)pBcl;
    __nv_bfloat16 *B3h  = (__nv_bfloat16*)pB3h,  *B3l  = (__nv_bfloat16*)pB3l;

    // dynamic SMEM: 2 stages * (2*A + 2*B) with 80B row stride
    constexpr int SM192 = 2 * (2 * 128 * 80 + 2 * 192 * 80);  // 102400
    constexpr int SM64  = 2 * (2 * 128 * 80 + 2 * 64 * 80);   // 61440
    cudaFuncSetAttribute(k_mma<192, 0>, cudaFuncAttributeMaxDynamicSharedMemorySize, SM192);
    cudaFuncSetAttribute(k_mma<64, 1>,  cudaFuncAttributeMaxDynamicSharedMemorySize, SM64);

    // --- CSR build (deterministic) ---
    k_zero_deg<<<(2 * Nn + 255) / 256, 256>>>();
    k_hist<<<(Ee + 255) / 256, 256>>>(erows, ecols);
    k_scan<<<2, 1024>>>();
    k_fill<<<(Ee + 255) / 256, 256>>>(erows, ecols, s1w, s2w);
    k_sortrows<<<(2 * Nn + 255) / 256, 256>>>();

    // --- weights + transpose ---
    k_wprep<<<(192 * K1 + 64 * K2 + 255) / 256, 256>>>(W_lat, W_units, W_fin);
    k_transpose<<<((long)Bb * Nn * Ff + 255) / 256, 256>>>(y);

    const int* rp1 = rp;       const int* rp2 = rp + (Nn + 1);
    const int* sr1 = csrc;     const int* sr2 = csrc + Ee;
    const float* w1 = cw;      const float* w2 = cw + Ee;

    // --- diffusion states (F width, shared by gconv1/gconv2) ---
    k_spmm<1><<<Nn, 512>>>(rp1, sr1, w1, x0,  nullptr, tmp,     A64h, A64l, 1, K1);
    k_spmm<1><<<Nn, 512>>>(rp1, sr1, w1, tmp, x0,      nullptr, A64h, A64l, 2, K1);
    k_spmm<1><<<Nn, 512>>>(rp2, sr2, w2, x0,  nullptr, tmp,     A64h, A64l, 3, K1);
    k_spmm<1><<<Nn, 512>>>(rp2, sr2, w2, tmp, x0,      nullptr, A64h, A64l, 4, K1);

    // --- fused gconv1+gconv2: [theta | c0] = act(A64 @ [W_lat | W_units] + b) ---
    k_mma<192, 0><<<ROWS / 128, 256, SM192>>>(A64h, A64l, K1, Bch, Bcl,
                                              b_lat, b_units, th, c0, A2h, A2l, nullptr);

    // --- gconv3 diffusion (U width) ---
    k_spmm<2><<<Nn, 512>>>(rp1, sr1, w1, c0,  nullptr, tmp,     A2h, A2l, 1, K2);
    k_spmm<2><<<Nn, 512>>>(rp1, sr1, w1, tmp, c0,      nullptr, A2h, A2l, 2, K2);
    k_spmm<2><<<Nn, 512>>>(rp2, sr2, w2, c0,  nullptr, tmp,     A2h, A2l, 3, K2);
    k_spmm<2><<<Nn, 512>>>(rp2, sr2, w2, tmp, c0,      nullptr, A2h, A2l, 4, K2);

    // --- gconv3 + fuse: out = -theta * tanh(A2 @ W_final + b_lat) ---
    k_mma<64, 1><<<ROWS / 128, 256, SM64>>>(A2h, A2l, K2, B3h, B3l,
                                            b_lat, nullptr, th, nullptr,
                                            nullptr, nullptr, out);
}